// round 12
// baseline (speedup 1.0000x reference)
#include <cuda_runtime.h>
#include <cuda_fp16.h>
#include <cstdint>
#include <cstddef>

// ============================================================================
// Windowed self-attention via mma.sync.m16n8k16 fp16 (split-fp32, fp32 acc).
// S-equiv = (x M^T + r) x^T  (M = Wq^T Wk, r = bq Wk; row-consts cancel in
// softmax). 4 GEMMs/window:
//   G3: vT = Wvh xh^T + bv (1-term)
//   G1: t  = x M^T + r     (3-term)
//   G2: S  = t x^T         (3-term, A = t register fragments)
//   G4: O  = Ph vT^T       (1-term, overlapped with next window's x load)
// Single launch: M / Wv images and r are built in a per-CTA prologue using
// the same tensor-core GEMM (no prep kernel, no global image round-trip).
// 8 warps x 16 rows, 256 thr, persistent CTAs, 2 barriers/window.
// ============================================================================

#define WIN 128
// smem layout (bytes from 1KB-aligned base)
#define XH   0
#define XL   32768
#define MH   65536
#define WVH  131072
#define VTB  163840
#define OFF_BV 196608
#define OFF_R  197120
#define SMEM_PAYLOAD 197632
#define SMEM_BYTES (SMEM_PAYLOAD + 1024)

__device__ __forceinline__ uint32_t smem_u32(const void* p) {
    uint32_t a;
    asm("{ .reg .u64 t; cvta.to.shared.u64 t, %1; cvt.u32.u64 %0, t; }" : "=r"(a) : "l"(p));
    return a;
}

// Tile: 128 rows x 128 fp16 (256B/row, 16 chunks of 16B), XOR-swizzled.
__device__ __forceinline__ uint32_t toff(int row, int byteCol) {
    int chunk = byteCol >> 4;
    return (uint32_t)(row * 256 + (((chunk ^ (row & 7)) << 4) | (byteCol & 15)));
}

__device__ __forceinline__ uint32_t pack2h(__half a, __half b) {
    return (uint32_t)__half_as_ushort(a) | ((uint32_t)__half_as_ushort(b) << 16);
}

__device__ __forceinline__ void ldsm4(uint32_t r[4], uint32_t addr) {
    asm volatile("ldmatrix.sync.aligned.m8n8.x4.shared.b16 {%0,%1,%2,%3}, [%4];"
                 : "=r"(r[0]), "=r"(r[1]), "=r"(r[2]), "=r"(r[3]) : "r"(addr));
}

__device__ __forceinline__ void mma16816(float* c, const uint32_t a[4],
                                         uint32_t b0, uint32_t b1) {
    asm volatile(
        "mma.sync.aligned.m16n8k16.row.col.f32.f16.f16.f32 "
        "{%0,%1,%2,%3}, {%4,%5,%6,%7}, {%8,%9}, {%0,%1,%2,%3};"
        : "+f"(c[0]), "+f"(c[1]), "+f"(c[2]), "+f"(c[3])
        : "r"(a[0]), "r"(a[1]), "r"(a[2]), "r"(a[3]), "r"(b0), "r"(b1));
}

// load + split one window of x into XH/XL (all 256 threads)
__device__ __forceinline__ void load_x(const float* __restrict__ xw, char* smem, int tid) {
#pragma unroll
    for (int i = 0; i < 16; i++) {
        int idx4 = i * 256 + tid;
        int row = idx4 >> 5, col4 = idx4 & 31;
        float4 v = reinterpret_cast<const float4*>(xw)[idx4];
        __half h0 = __float2half_rn(v.x), h1 = __float2half_rn(v.y);
        __half h2 = __float2half_rn(v.z), h3 = __float2half_rn(v.w);
        uint32_t off = toff(row, col4 * 8);
        *reinterpret_cast<uint2*>(smem + XH + off) =
            make_uint2(pack2h(h0, h1), pack2h(h2, h3));
        *reinterpret_cast<uint2*>(smem + XL + off) = make_uint2(
            pack2h(__float2half_rn(v.x - __half2float(h0)),
                   __float2half_rn(v.y - __half2float(h1))),
            pack2h(__float2half_rn(v.z - __half2float(h2)),
                   __float2half_rn(v.w - __half2float(h3))));
    }
}

// ---- 3-term GEMM: A smem hi/lo (aBase, aBase+32KB), B smem hi/lo ----
__device__ __forceinline__ void gemm3_sa(float (&c)[16][4],
                                         uint32_t aBase, uint32_t bBase,
                                         int arow, int acb, int brl, int bcb) {
#pragma unroll
    for (int nt = 0; nt < 16; nt++)
#pragma unroll
        for (int i = 0; i < 4; i++) c[nt][i] = 0.0f;
#pragma unroll 1
    for (int kt = 0; kt < 8; kt++) {
        uint32_t ah[4], al[4];
        {
            uint32_t off = (uint32_t)(arow * 256 + (((kt * 2 + acb) ^ (arow & 7)) << 4));
            ldsm4(ah, aBase + off);
            ldsm4(al, aBase + 32768u + off);
        }
#pragma unroll
        for (int ng = 0; ng < 8; ng++) {
            int brow = ng * 16 + brl;
            uint32_t boff = (uint32_t)(brow * 256 + (((kt * 2 + bcb) ^ (brow & 7)) << 4));
            uint32_t bh[4], bl[4];
            ldsm4(bh, bBase + boff);
            ldsm4(bl, bBase + 32768u + boff);
#pragma unroll
            for (int s = 0; s < 2; s++) {
                float* cc = c[ng * 2 + s];
                mma16816(cc, ah, bh[2 * s], bh[2 * s + 1]);
                mma16816(cc, ah, bl[2 * s], bl[2 * s + 1]);
                mma16816(cc, al, bh[2 * s], bh[2 * s + 1]);
            }
        }
    }
}

// ---- 3-term GEMM: A register fragments (hi/lo), B smem hi/lo ----
__device__ __forceinline__ void gemm3_ra(float (&c)[16][4],
                                         const uint32_t (&th)[16][2],
                                         const uint32_t (&tl)[16][2],
                                         uint32_t bBase, int brl, int bcb) {
#pragma unroll
    for (int nt = 0; nt < 16; nt++)
#pragma unroll
        for (int i = 0; i < 4; i++) c[nt][i] = 0.0f;
#pragma unroll
    for (int kt = 0; kt < 8; kt++) {
        uint32_t ah[4] = {th[2 * kt][0], th[2 * kt][1], th[2 * kt + 1][0], th[2 * kt + 1][1]};
        uint32_t al[4] = {tl[2 * kt][0], tl[2 * kt][1], tl[2 * kt + 1][0], tl[2 * kt + 1][1]};
#pragma unroll
        for (int ng = 0; ng < 8; ng++) {
            int brow = ng * 16 + brl;
            uint32_t boff = (uint32_t)(brow * 256 + (((kt * 2 + bcb) ^ (brow & 7)) << 4));
            uint32_t bh[4], bl[4];
            ldsm4(bh, bBase + boff);
            ldsm4(bl, bBase + 32768u + boff);
#pragma unroll
            for (int s = 0; s < 2; s++) {
                float* cc = c[ng * 2 + s];
                mma16816(cc, ah, bh[2 * s], bh[2 * s + 1]);
                mma16816(cc, ah, bl[2 * s], bl[2 * s + 1]);
                mma16816(cc, al, bh[2 * s], bh[2 * s + 1]);
            }
        }
    }
}

// ---- 1-term GEMM: A smem single image, B smem single image ----
__device__ __forceinline__ void gemm1_sa(float (&c)[16][4],
                                         uint32_t aBase, uint32_t bBase,
                                         int arow, int acb, int brl, int bcb) {
#pragma unroll
    for (int nt = 0; nt < 16; nt++)
#pragma unroll
        for (int i = 0; i < 4; i++) c[nt][i] = 0.0f;
#pragma unroll 1
    for (int kt = 0; kt < 8; kt++) {
        uint32_t ah[4];
        {
            uint32_t off = (uint32_t)(arow * 256 + (((kt * 2 + acb) ^ (arow & 7)) << 4));
            ldsm4(ah, aBase + off);
        }
#pragma unroll
        for (int ng = 0; ng < 8; ng++) {
            int brow = ng * 16 + brl;
            uint32_t boff = (uint32_t)(brow * 256 + (((kt * 2 + bcb) ^ (brow & 7)) << 4));
            uint32_t bh[4];
            ldsm4(bh, bBase + boff);
#pragma unroll
            for (int s = 0; s < 2; s++)
                mma16816(c[ng * 2 + s], ah, bh[2 * s], bh[2 * s + 1]);
        }
    }
}

// ---- 1-term GEMM: A register fragments (hi only), B smem single image ----
__device__ __forceinline__ void gemm1_ra(float (&c)[16][4],
                                         const uint32_t (&th)[16][2],
                                         uint32_t bBase, int brl, int bcb) {
#pragma unroll
    for (int nt = 0; nt < 16; nt++)
#pragma unroll
        for (int i = 0; i < 4; i++) c[nt][i] = 0.0f;
#pragma unroll
    for (int kt = 0; kt < 8; kt++) {
        uint32_t ah[4] = {th[2 * kt][0], th[2 * kt][1], th[2 * kt + 1][0], th[2 * kt + 1][1]};
#pragma unroll
        for (int ng = 0; ng < 8; ng++) {
            int brow = ng * 16 + brl;
            uint32_t boff = (uint32_t)(brow * 256 + (((kt * 2 + bcb) ^ (brow & 7)) << 4));
            uint32_t bh[4];
            ldsm4(bh, bBase + boff);
#pragma unroll
            for (int s = 0; s < 2; s++)
                mma16816(c[ng * 2 + s], ah, bh[2 * s], bh[2 * s + 1]);
        }
    }
}

// pack C fragments into hi-only fp16 A-fragments (for P)
__device__ __forceinline__ void pack_hi(const float (&c)[16][4], uint32_t (&h)[16][2]) {
#pragma unroll
    for (int nt = 0; nt < 16; nt++)
#pragma unroll
        for (int j = 0; j < 2; j++)
            h[nt][j] = pack2h(__float2half_rn(c[nt][2 * j]),
                              __float2half_rn(c[nt][2 * j + 1]));
}

// pack C fragments into hi/lo fp16 A-fragments, adding per-column bias r (t)
__device__ __forceinline__ void pack_split_bias(const float (&c)[16][4],
                                                uint32_t (&h)[16][2], uint32_t (&l)[16][2],
                                                const float* sr, int cq) {
#pragma unroll
    for (int nt = 0; nt < 16; nt++) {
        float rA = sr[nt * 8 + cq], rB = sr[nt * 8 + cq + 1];
#pragma unroll
        for (int j = 0; j < 2; j++) {
            float v0 = c[nt][2 * j] + rA, v1 = c[nt][2 * j + 1] + rB;
            __half h0 = __float2half_rn(v0), h1 = __float2half_rn(v1);
            h[nt][j] = pack2h(h0, h1);
            l[nt][j] = pack2h(__float2half_rn(v0 - __half2float(h0)),
                              __float2half_rn(v1 - __half2float(h1)));
        }
    }
}

__global__ void __launch_bounds__(256, 1)
win_attn(const float* __restrict__ x,
         const float* __restrict__ Wq, const float* __restrict__ bq,
         const float* __restrict__ Wk, const float* __restrict__ Wv,
         const float* __restrict__ bv,
         float* __restrict__ out, int nwin) {
    extern __shared__ char smem_raw[];
    uint32_t sraw = smem_u32(smem_raw);
    uint32_t sb = (sraw + 1023u) & ~1023u;
    char* smem = smem_raw + (sb - sraw);

    const int tid = threadIdx.x, wid = tid >> 5, lane = tid & 31;

    float* sbv = reinterpret_cast<float*>(smem + OFF_BV);
    float* sr  = reinterpret_cast<float*>(smem + OFF_R);

    // ldmatrix lane mappings
    const int arl = (lane & 7) + ((lane >> 3) & 1) * 8, acb = (lane >> 4) & 1;
    const int brl = (lane & 7) + ((lane >> 4) & 1) * 8, bcb = (lane >> 3) & 1;
    const int rq = lane >> 2, cq = 2 * (lane & 3);
    const int rowBase = wid * 16;
    const int arow = rowBase + arl;

    float c[16][4];
    uint32_t fh[16][2], fl[16][2];   // A-fragments: t (hi/lo), then P (hi)

    // ======================= prologue: build M, Wv, r =======================
    // Wq^T split images -> XH/XL ; Wk^T split images -> MH/MH+32K ;
    // Wv hi image -> WVH (all transposed/converted from gmem, one-time)
#pragma unroll 1
    for (int i = 0; i < 64; i++) {
        int idx = i * 256 + tid;              // idx = d*128 + e
        int d = idx >> 7, e = idx & 127;
        float q = Wq[idx];
        float k = Wk[idx];
        uint32_t o = toff(e, d * 2);          // transposed: row e, col d
        __half qh = __float2half_rn(q);
        *reinterpret_cast<__half*>(smem + XH + o) = qh;
        *reinterpret_cast<__half*>(smem + XL + o) = __float2half_rn(q - __half2float(qh));
        __half kh = __float2half_rn(k);
        *reinterpret_cast<__half*>(smem + MH + o) = kh;
        *reinterpret_cast<__half*>(smem + MH + 32768 + o) =
            __float2half_rn(k - __half2float(kh));
        // Wv hi image: row d, col e (direct)
        *reinterpret_cast<__half*>(smem + WVH + toff(d, e * 2)) = __float2half_rn(Wv[idx]);
    }
    // r[f] = sum_d bq[d] Wk[d,f]  and bv into smem
    if (tid < 128) {
        float acc = 0.0f;
#pragma unroll 8
        for (int d = 0; d < 128; d++)
            acc += bq[d] * Wk[d * 128 + tid];
        sr[tid] = acc;
        sbv[tid] = bv[tid];
    }
    __syncthreads();

    // M = Wq^T Wk via 3-term tensor GEMM: A = Wq^T (XH/XL), B = Wk^T (MH pair)
    gemm3_sa(c, sb + XH, sb + MH, arow, acb, brl, bcb);
    __syncthreads();                      // all Wk^T reads complete

    // write M split images into MH / MH+32K (overwriting Wk^T)
#pragma unroll
    for (int h = 0; h < 2; h++) {
        int row = rowBase + h * 8 + rq;   // e-row of M
#pragma unroll
        for (int nt = 0; nt < 16; nt++) {
            int col = nt * 8 + cq;        // f-col
            float v0 = c[nt][2 * h], v1 = c[nt][2 * h + 1];
            __half h0 = __float2half_rn(v0), h1 = __float2half_rn(v1);
            // B-image for G1 is indexed by row f, col e -> store transposed
            uint32_t o0 = toff(col, row * 2), o1 = toff(col + 1, row * 2);
            *reinterpret_cast<__half*>(smem + MH + o0) = h0;
            *reinterpret_cast<__half*>(smem + MH + 32768 + o0) =
                __float2half_rn(v0 - __half2float(h0));
            *reinterpret_cast<__half*>(smem + MH + o1) = h1;
            *reinterpret_cast<__half*>(smem + MH + 32768 + o1) =
                __float2half_rn(v1 - __half2float(h1));
        }
    }

    // ============================ main loop =================================
    int w = blockIdx.x;
    __syncthreads();                      // M images complete before overwrite XH
    if (w < nwin) load_x(x + (size_t)w * (WIN * 128), smem, tid);
    __syncthreads();                      // x(w0), images, biases ready

    while (w < nwin) {
        // ---- G3 (1-term): vT = Wvh xh^T ; +bv row ; -> VTB ----
        gemm1_sa(c, sb + WVH, sb + XH, arow, acb, brl, bcb);
#pragma unroll
        for (int h = 0; h < 2; h++) {
            int row = rowBase + h * 8 + rq;
            float br = sbv[row];
#pragma unroll
            for (int nt = 0; nt < 16; nt++) {
                int col = nt * 8 + cq;
                *reinterpret_cast<uint32_t*>(smem + VTB + toff(row, col * 2)) =
                    pack2h(__float2half_rn(c[nt][2 * h] + br),
                           __float2half_rn(c[nt][2 * h + 1] + br));
            }
        }

        // ---- G1 (3-term): t = x M^T ; t += r ; -> register fragments ----
        gemm3_sa(c, sb + XH, sb + MH, arow, acb, brl, bcb);
        pack_split_bias(c, fh, fl, sr, cq);

        // ---- G2 (3-term): S = t x^T (A = t regs, B = XH/XL) ----
        gemm3_ra(c, fh, fl, sb + XH, brl, bcb);

        // softmax on c -> P fragments (hi only)
#pragma unroll
        for (int h = 0; h < 2; h++) {
            float m = -1e30f;
#pragma unroll
            for (int nt = 0; nt < 16; nt++)
                m = fmaxf(m, fmaxf(c[nt][2 * h], c[nt][2 * h + 1]));
            m = fmaxf(m, __shfl_xor_sync(0xffffffffu, m, 1));
            m = fmaxf(m, __shfl_xor_sync(0xffffffffu, m, 2));
            float s = 0.0f;
#pragma unroll
            for (int nt = 0; nt < 16; nt++) {
                float e0 = __expf(c[nt][2 * h] - m);
                float e1 = __expf(c[nt][2 * h + 1] - m);
                c[nt][2 * h] = e0;
                c[nt][2 * h + 1] = e1;
                s += e0 + e1;
            }
            s += __shfl_xor_sync(0xffffffffu, s, 1);
            s += __shfl_xor_sync(0xffffffffu, s, 2);
            float inv = 1.0f / s;
#pragma unroll
            for (int nt = 0; nt < 16; nt++) {
                c[nt][2 * h] *= inv;
                c[nt][2 * h + 1] *= inv;
            }
        }
        pack_hi(c, fh);                  // P fragments (hi only)
        __syncthreads();                 // (2) vT visible; XH/XL dead everywhere

        // ---- overlap: load x for next window while G4 runs ----
        int wn = w + gridDim.x;
        if (wn < nwin) load_x(x + (size_t)wn * (WIN * 128), smem, tid);

        // ---- G4 (1-term): O = Ph vT^T -> out ----
        gemm1_ra(c, fh, sb + VTB, brl, bcb);
        {
            float* outw = out + (size_t)w * (WIN * 128);
#pragma unroll
            for (int h = 0; h < 2; h++) {
                int row = rowBase + h * 8 + rq;
#pragma unroll
                for (int nt = 0; nt < 16; nt++) {
                    int col = nt * 8 + cq;
                    *reinterpret_cast<float2*>(outw + row * 128 + col) =
                        make_float2(c[nt][2 * h], c[nt][2 * h + 1]);
                }
            }
        }
        __syncthreads();                 // (1) new x ready; VTB dead

        w = wn;
    }
}

extern "C" void kernel_launch(void* const* d_in, const int* in_sizes, int n_in,
                              void* d_out, int out_size) {
    const float* x  = (const float*)d_in[0];
    const float* Wq = (const float*)d_in[1];
    const float* bq = (const float*)d_in[2];
    const float* Wk = (const float*)d_in[3];
    const float* Wv = (const float*)d_in[5];
    const float* bv = (const float*)d_in[6];
    float* out = (float*)d_out;

    int nwin = in_sizes[0] / (WIN * 128);

    cudaFuncSetAttribute(win_attn, cudaFuncAttributeMaxDynamicSharedMemorySize, SMEM_BYTES);
    int grid = nwin < 148 ? nwin : 148;
    win_attn<<<grid, 256, SMEM_BYTES>>>(x, Wq, bq, Wk, Wv, bv, out, nwin);
}

// round 13
// speedup vs baseline: 1.1426x; 1.1426x over previous
#include <cuda_runtime.h>
#include <cuda_fp16.h>
#include <cstdint>
#include <cstddef>

// ============================================================================
// Windowed self-attention via mma.sync.m16n8k16 fp16 (split-fp32, fp32 acc).
// S-equiv = (x M^T + r) x^T  (M = Wq^T Wk, r = bq Wk; row-consts cancel in
// softmax). 4 GEMMs/window:
//   G1: t  = x M^T + r     (3-term)  -> smem T images (hi/lo)
//   G2: S  = t x^T         (3-term, A = T images)
//   G3: vT = Wvh xh^T + bv (1-term)  -> VTB (= T_LO reuse)
//   G4: O  = Ph vT^T       (1-term, A = PIMG (= T_HI reuse))
// 16 warps x (16 rows x 64 cols), 512 threads, persistent CTAs.
// Next window's x load overlapped with G4.
// ============================================================================

#define WIN 128
// smem layout (bytes from 1KB-aligned base)
#define XH    0
#define XL    32768
#define MH    65536          // M hi ; M lo at +32768
#define WVH   131072
#define T_HI  163840         // t hi ; later reused as PIMG
#define T_LO  196608         // t lo ; later reused as VTB
#define OFF_BV   229376
#define OFF_R    229888
#define OFF_SRED 230400      // 256 floats (row*2 + half)
#define SMEM_PAYLOAD 231424
#define SMEM_BYTES 232448    // payload + <=1KB alignment slack (= 227KB optin)

__device__ __forceinline__ uint32_t smem_u32(const void* p) {
    uint32_t a;
    asm("{ .reg .u64 t; cvta.to.shared.u64 t, %1; cvt.u32.u64 %0, t; }" : "=r"(a) : "l"(p));
    return a;
}

// Tile: 128 rows x 128 fp16 (256B/row, 16 chunks of 16B), XOR-swizzled.
__device__ __forceinline__ uint32_t toff(int row, int byteCol) {
    int chunk = byteCol >> 4;
    return (uint32_t)(row * 256 + (((chunk ^ (row & 7)) << 4) | (byteCol & 15)));
}

__device__ __forceinline__ uint32_t pack2h(__half a, __half b) {
    return (uint32_t)__half_as_ushort(a) | ((uint32_t)__half_as_ushort(b) << 16);
}

__device__ __forceinline__ void ldsm4(uint32_t r[4], uint32_t addr) {
    asm volatile("ldmatrix.sync.aligned.m8n8.x4.shared.b16 {%0,%1,%2,%3}, [%4];"
                 : "=r"(r[0]), "=r"(r[1]), "=r"(r[2]), "=r"(r[3]) : "r"(addr));
}

__device__ __forceinline__ void mma16816(float* c, const uint32_t a[4],
                                         uint32_t b0, uint32_t b1) {
    asm volatile(
        "mma.sync.aligned.m16n8k16.row.col.f32.f16.f16.f32 "
        "{%0,%1,%2,%3}, {%4,%5,%6,%7}, {%8,%9}, {%0,%1,%2,%3};"
        : "+f"(c[0]), "+f"(c[1]), "+f"(c[2]), "+f"(c[3])
        : "r"(a[0]), "r"(a[1]), "r"(a[2]), "r"(a[3]), "r"(b0), "r"(b1));
}

// Pre-split + pre-swizzled images: [M^T hi, M^T lo, Wv hi]
__device__ __align__(16) __half g_img[3 * 16384];
__device__ float g_r[128];

// ---- prep kernel (separate launch; proven cheap): M image, Wv image, r ----
__global__ void prep_all(const float* __restrict__ Wq, const float* __restrict__ bq,
                         const float* __restrict__ Wk, const float* __restrict__ Wv) {
    __shared__ float wkcol[128];
    __shared__ float red[4];
    int f = blockIdx.x, e = threadIdx.x;
    wkcol[e] = Wk[e * 128 + f];
    __syncthreads();
    float acc = 0.0f;
#pragma unroll 8
    for (int d = 0; d < 128; d++)
        acc += Wq[d * 128 + e] * wkcol[d];
    uint32_t o = toff(f, e * 2) >> 1;
    {
        __half h = __float2half_rn(acc);
        g_img[o] = h;
        g_img[16384 + o] = __float2half_rn(acc - __half2float(h));
    }
    g_img[2 * 16384 + o] = __float2half_rn(Wv[f * 128 + e]);
    float p = bq[e] * wkcol[e];
#pragma unroll
    for (int m = 16; m >= 1; m >>= 1) p += __shfl_xor_sync(0xffffffffu, p, m);
    if ((e & 31) == 0) red[e >> 5] = p;
    __syncthreads();
    if (e == 0) g_r[f] = red[0] + red[1] + red[2] + red[3];
}

// copy pre-swizzled 32KB image into smem (512 threads)
__device__ __forceinline__ void copy_img32(char* dst, int imgIdx, int tid) {
    const uint4* s4 = reinterpret_cast<const uint4*>(g_img + (size_t)imgIdx * 16384);
    uint4* d4 = reinterpret_cast<uint4*>(dst);
#pragma unroll
    for (int i = 0; i < 4; i++) d4[tid + i * 512] = s4[tid + i * 512];
}

// load + split one window of x into XH/XL (512 threads)
__device__ __forceinline__ void load_x(const float* __restrict__ xw, char* smem, int tid) {
#pragma unroll
    for (int i = 0; i < 8; i++) {
        int idx4 = i * 512 + tid;
        int row = idx4 >> 5, col4 = idx4 & 31;
        float4 v = reinterpret_cast<const float4*>(xw)[idx4];
        __half h0 = __float2half_rn(v.x), h1 = __float2half_rn(v.y);
        __half h2 = __float2half_rn(v.z), h3 = __float2half_rn(v.w);
        uint32_t off = toff(row, col4 * 8);
        *reinterpret_cast<uint2*>(smem + XH + off) =
            make_uint2(pack2h(h0, h1), pack2h(h2, h3));
        *reinterpret_cast<uint2*>(smem + XL + off) = make_uint2(
            pack2h(__float2half_rn(v.x - __half2float(h0)),
                   __float2half_rn(v.y - __half2float(h1))),
            pack2h(__float2half_rn(v.z - __half2float(h2)),
                   __float2half_rn(v.w - __half2float(h3))));
    }
}

// ---- 3-term GEMM (N=64 slice): A smem hi/lo, B smem hi/lo rows bRow0+ ----
__device__ __forceinline__ void gemm3_s4(float (&c)[8][4],
                                         uint32_t aBase, uint32_t bBase,
                                         int arow, int acb, int brl, int bcb, int bRow0) {
#pragma unroll
    for (int nt = 0; nt < 8; nt++)
#pragma unroll
        for (int i = 0; i < 4; i++) c[nt][i] = 0.0f;
#pragma unroll 1
    for (int kt = 0; kt < 8; kt++) {
        uint32_t ah[4], al[4];
        {
            uint32_t off = (uint32_t)(arow * 256 + (((kt * 2 + acb) ^ (arow & 7)) << 4));
            ldsm4(ah, aBase + off);
            ldsm4(al, aBase + 32768u + off);
        }
#pragma unroll
        for (int ng = 0; ng < 4; ng++) {
            int brow = bRow0 + ng * 16 + brl;
            uint32_t boff = (uint32_t)(brow * 256 + (((kt * 2 + bcb) ^ (brow & 7)) << 4));
            uint32_t bh[4], bl[4];
            ldsm4(bh, bBase + boff);
            ldsm4(bl, bBase + 32768u + boff);
#pragma unroll
            for (int s = 0; s < 2; s++) {
                float* cc = c[ng * 2 + s];
                mma16816(cc, ah, bh[2 * s], bh[2 * s + 1]);
                mma16816(cc, ah, bl[2 * s], bl[2 * s + 1]);
                mma16816(cc, al, bh[2 * s], bh[2 * s + 1]);
            }
        }
    }
}

// ---- 1-term GEMM (N=64 slice): A smem single, B smem single rows bRow0+ ----
__device__ __forceinline__ void gemm1_s4(float (&c)[8][4],
                                         uint32_t aBase, uint32_t bBase,
                                         int arow, int acb, int brl, int bcb, int bRow0) {
#pragma unroll
    for (int nt = 0; nt < 8; nt++)
#pragma unroll
        for (int i = 0; i < 4; i++) c[nt][i] = 0.0f;
#pragma unroll 1
    for (int kt = 0; kt < 8; kt++) {
        uint32_t ah[4];
        {
            uint32_t off = (uint32_t)(arow * 256 + (((kt * 2 + acb) ^ (arow & 7)) << 4));
            ldsm4(ah, aBase + off);
        }
#pragma unroll
        for (int ng = 0; ng < 4; ng++) {
            int brow = bRow0 + ng * 16 + brl;
            uint32_t boff = (uint32_t)(brow * 256 + (((kt * 2 + bcb) ^ (brow & 7)) << 4));
            uint32_t bh[4];
            ldsm4(bh, bBase + boff);
#pragma unroll
            for (int s = 0; s < 2; s++)
                mma16816(c[ng * 2 + s], ah, bh[2 * s], bh[2 * s + 1]);
        }
    }
}

__global__ void __launch_bounds__(512, 1)
win_attn(const float* __restrict__ x, const float* __restrict__ bv,
         float* __restrict__ out, int nwin) {
    extern __shared__ char smem_raw[];
    uint32_t sraw = smem_u32(smem_raw);
    uint32_t sb = (sraw + 1023u) & ~1023u;
    char* smem = smem_raw + (sb - sraw);

    const int tid = threadIdx.x, wid = tid >> 5, lane = tid & 31;
    const int m8 = wid & 7, nh = wid >> 3;

    float* sbv  = reinterpret_cast<float*>(smem + OFF_BV);
    float* sr   = reinterpret_cast<float*>(smem + OFF_R);
    float* sred = reinterpret_cast<float*>(smem + OFF_SRED);
    if (tid < 128) {
        sbv[tid] = bv[tid];
        sr[tid] = g_r[tid];
    }
    copy_img32(smem + MH, 0, tid);
    copy_img32(smem + MH + 32768, 1, tid);
    copy_img32(smem + WVH, 2, tid);

    // ldmatrix lane mappings
    const int arl = (lane & 7) + ((lane >> 3) & 1) * 8, acb = (lane >> 4) & 1;
    const int brl = (lane & 7) + ((lane >> 4) & 1) * 8, bcb = (lane >> 3) & 1;
    const int rq = lane >> 2, cq = 2 * (lane & 3);
    const int rowBase = m8 * 16;
    const int colBase = nh * 64;
    const int arow = rowBase + arl;

    float c[8][4];

    int w = blockIdx.x;
    if (w < nwin) load_x(x + (size_t)w * (WIN * 128), smem, tid);
    __syncthreads();                     // x(w0), images, biases ready

    while (w < nwin) {
        // ---- G1 (3-term): t = x M^T (+r) -> T_HI/T_LO images ----
        gemm3_s4(c, sb + XH, sb + MH, arow, acb, brl, bcb, colBase);
#pragma unroll
        for (int h = 0; h < 2; h++) {
            int row = rowBase + h * 8 + rq;
#pragma unroll
            for (int nt = 0; nt < 8; nt++) {
                int col = colBase + nt * 8 + cq;
                float v0 = c[nt][2 * h] + sr[col];
                float v1 = c[nt][2 * h + 1] + sr[col + 1];
                __half h0 = __float2half_rn(v0), h1 = __float2half_rn(v1);
                uint32_t o = toff(row, col * 2);
                *reinterpret_cast<uint32_t*>(smem + T_HI + o) = pack2h(h0, h1);
                *reinterpret_cast<uint32_t*>(smem + T_LO + o) =
                    pack2h(__float2half_rn(v0 - __half2float(h0)),
                           __float2half_rn(v1 - __half2float(h1)));
            }
        }
        __syncthreads();                 // (1) T images ready

        // ---- G2 (3-term): S = t x^T  (A = T images, B = XH/XL) ----
        gemm3_s4(c, sb + T_HI, sb + XH, arow, acb, brl, bcb, colBase);

        // ---- softmax with cross-half reduction (rows split over nh) ----
        float mrow[2], inv[2];
#pragma unroll
        for (int h = 0; h < 2; h++) {
            float m = -1e30f;
#pragma unroll
            for (int nt = 0; nt < 8; nt++)
                m = fmaxf(m, fmaxf(c[nt][2 * h], c[nt][2 * h + 1]));
            m = fmaxf(m, __shfl_xor_sync(0xffffffffu, m, 1));
            m = fmaxf(m, __shfl_xor_sync(0xffffffffu, m, 2));
            if ((lane & 3) == 0)
                sred[(rowBase + h * 8 + rq) * 2 + nh] = m;
            mrow[h] = m;
        }
        __syncthreads();                 // (2) partial maxes visible
#pragma unroll
        for (int h = 0; h < 2; h++) {
            int row = rowBase + h * 8 + rq;
            mrow[h] = fmaxf(sred[row * 2], sred[row * 2 + 1]);
        }
        __syncthreads();                 // (3) all maxes read; buffer reusable
#pragma unroll
        for (int h = 0; h < 2; h++) {
            float s = 0.0f;
#pragma unroll
            for (int nt = 0; nt < 8; nt++) {
                float e0 = __expf(c[nt][2 * h] - mrow[h]);
                float e1 = __expf(c[nt][2 * h + 1] - mrow[h]);
                c[nt][2 * h] = e0;
                c[nt][2 * h + 1] = e1;
                s += e0 + e1;
            }
            s += __shfl_xor_sync(0xffffffffu, s, 1);
            s += __shfl_xor_sync(0xffffffffu, s, 2);
            if ((lane & 3) == 0)
                sred[(rowBase + h * 8 + rq) * 2 + nh] = s;
        }
        __syncthreads();                 // (4) partial sums visible
#pragma unroll
        for (int h = 0; h < 2; h++) {
            int row = rowBase + h * 8 + rq;
            inv[h] = 1.0f / (sred[row * 2] + sred[row * 2 + 1]);
        }

        // ---- P (hi) -> PIMG (= T_HI; all G2 A-reads finished at bar 2) ----
#pragma unroll
        for (int h = 0; h < 2; h++) {
            int row = rowBase + h * 8 + rq;
#pragma unroll
            for (int nt = 0; nt < 8; nt++) {
                int col = colBase + nt * 8 + cq;
                *reinterpret_cast<uint32_t*>(smem + T_HI + toff(row, col * 2)) =
                    pack2h(__float2half_rn(c[nt][2 * h] * inv[h]),
                           __float2half_rn(c[nt][2 * h + 1] * inv[h]));
            }
        }

        // ---- G3 (1-term): vT = Wvh xh^T (+bv) -> VTB (= T_LO) ----
        gemm1_s4(c, sb + WVH, sb + XH, arow, acb, brl, bcb, colBase);
#pragma unroll
        for (int h = 0; h < 2; h++) {
            int row = rowBase + h * 8 + rq;
            float br = sbv[row];
#pragma unroll
            for (int nt = 0; nt < 8; nt++) {
                int col = colBase + nt * 8 + cq;
                *reinterpret_cast<uint32_t*>(smem + T_LO + toff(row, col * 2)) =
                    pack2h(__float2half_rn(c[nt][2 * h] + br),
                           __float2half_rn(c[nt][2 * h + 1] + br));
            }
        }
        __syncthreads();                 // (5) PIMG + VTB ready; X dead

        // ---- overlap: load x for next window while G4 runs ----
        int wn = w + gridDim.x;
        if (wn < nwin) load_x(x + (size_t)wn * (WIN * 128), smem, tid);

        // ---- G4 (1-term): O = Ph vT^T -> out ----
        gemm1_s4(c, sb + T_HI, sb + T_LO, arow, acb, brl, bcb, colBase);
        {
            float* outw = out + (size_t)w * (WIN * 128);
#pragma unroll
            for (int h = 0; h < 2; h++) {
                int row = rowBase + h * 8 + rq;
#pragma unroll
                for (int nt = 0; nt < 8; nt++) {
                    int col = colBase + nt * 8 + cq;
                    *reinterpret_cast<float2*>(outw + row * 128 + col) =
                        make_float2(c[nt][2 * h], c[nt][2 * h + 1]);
                }
            }
        }
        __syncthreads();                 // (6) new x ready; PIMG/VTB dead

        w = wn;
    }
}

extern "C" void kernel_launch(void* const* d_in, const int* in_sizes, int n_in,
                              void* d_out, int out_size) {
    const float* x  = (const float*)d_in[0];
    const float* Wq = (const float*)d_in[1];
    const float* bq = (const float*)d_in[2];
    const float* Wk = (const float*)d_in[3];
    const float* Wv = (const float*)d_in[5];
    const float* bv = (const float*)d_in[6];
    float* out = (float*)d_out;

    int nwin = in_sizes[0] / (WIN * 128);

    prep_all<<<128, 128>>>(Wq, bq, Wk, Wv);

    cudaFuncSetAttribute(win_attn, cudaFuncAttributeMaxDynamicSharedMemorySize, SMEM_BYTES);
    int grid = nwin < 148 ? nwin : 148;
    win_attn<<<grid, 512, SMEM_BYTES>>>(x, bv, out, nwin);
}

// round 15
// speedup vs baseline: 1.1553x; 1.0112x over previous
#include <cuda_runtime.h>
#include <cuda_fp16.h>
#include <cstdint>
#include <cstddef>

// ============================================================================
// Windowed self-attention via mma.sync.m16n8k16 fp16 (split-fp32, fp32 acc).
// S-equiv = (x M^T + r) x^T. 4 GEMMs/window:
//   G1: t  = x M^T + r     (3-term) -> T_HI/T_LO
//   G2: S  = t x^T         (3-term, A = T images)
//   G3: vT = Wvh xh^T + bv (1-term) -> T_LO reuse (tl dead post-G2)
//   G4: O  = Ph vT^T       (1-term, A = P image (T_HI reuse), B = vT)
// Decomposition (m4,n2): 8 warps, warp = 32 rows x 64 cols -> minimal smem
// traffic. 4 barriers/window (T and P images are cross-warp in k).
// Next window's x load overlapped with G4. 256 threads, persistent CTAs.
// ============================================================================

#define WIN 128
// smem layout (bytes from 1KB-aligned base)
#define XH    0
#define XL    32768
#define MH    65536          // M hi ; M lo at +32768
#define WVH   131072
#define T_HI  163840         // t hi ; later P image
#define T_LO  196608         // t lo ; later vT image
#define OFF_SRED 229376      // 128 rows x {m0,s0,m1,s1} = 2KB
#define SMEM_PAYLOAD 231424
#define SMEM_BYTES 232448    // payload + <=1KB alignment slack (227KB opt-in)

__device__ __forceinline__ uint32_t smem_u32(const void* p) {
    uint32_t a;
    asm("{ .reg .u64 t; cvta.to.shared.u64 t, %1; cvt.u32.u64 %0, t; }" : "=r"(a) : "l"(p));
    return a;
}

// Tile: 128 rows x 128 fp16 (256B/row, 16 chunks of 16B), XOR-swizzled.
__device__ __forceinline__ uint32_t toff(int row, int byteCol) {
    int chunk = byteCol >> 4;
    return (uint32_t)(row * 256 + (((chunk ^ (row & 7)) << 4) | (byteCol & 15)));
}

__device__ __forceinline__ uint32_t pack2h(__half a, __half b) {
    return (uint32_t)__half_as_ushort(a) | ((uint32_t)__half_as_ushort(b) << 16);
}

__device__ __forceinline__ void ldsm4(uint32_t r[4], uint32_t addr) {
    asm volatile("ldmatrix.sync.aligned.m8n8.x4.shared.b16 {%0,%1,%2,%3}, [%4];"
                 : "=r"(r[0]), "=r"(r[1]), "=r"(r[2]), "=r"(r[3]) : "r"(addr));
}

__device__ __forceinline__ void mma16816(float* c, const uint32_t a[4],
                                         uint32_t b0, uint32_t b1) {
    asm volatile(
        "mma.sync.aligned.m16n8k16.row.col.f32.f16.f16.f32 "
        "{%0,%1,%2,%3}, {%4,%5,%6,%7}, {%8,%9}, {%0,%1,%2,%3};"
        : "+f"(c[0]), "+f"(c[1]), "+f"(c[2]), "+f"(c[3])
        : "r"(a[0]), "r"(a[1]), "r"(a[2]), "r"(a[3]), "r"(b0), "r"(b1));
}

// Pre-split + pre-swizzled images: [M^T hi, M^T lo, Wv hi]
__device__ __align__(16) __half g_img[3 * 16384];
__device__ float g_r[128];

// ---- prep kernel: M image, Wv image, r vector ----
__global__ void prep_all(const float* __restrict__ Wq, const float* __restrict__ bq,
                         const float* __restrict__ Wk, const float* __restrict__ Wv) {
    __shared__ float wkcol[128];
    __shared__ float red[4];
    int f = blockIdx.x, e = threadIdx.x;
    wkcol[e] = Wk[e * 128 + f];
    __syncthreads();
    float acc = 0.0f;
#pragma unroll 8
    for (int d = 0; d < 128; d++)
        acc += Wq[d * 128 + e] * wkcol[d];
    uint32_t o = toff(f, e * 2) >> 1;
    {
        __half h = __float2half_rn(acc);
        g_img[o] = h;
        g_img[16384 + o] = __float2half_rn(acc - __half2float(h));
    }
    g_img[2 * 16384 + o] = __float2half_rn(Wv[f * 128 + e]);
    float p = bq[e] * wkcol[e];
#pragma unroll
    for (int m = 16; m >= 1; m >>= 1) p += __shfl_xor_sync(0xffffffffu, p, m);
    if ((e & 31) == 0) red[e >> 5] = p;
    __syncthreads();
    if (e == 0) g_r[f] = red[0] + red[1] + red[2] + red[3];
}

// copy pre-swizzled 32KB image into smem (256 threads)
__device__ __forceinline__ void copy_img32(char* dst, int imgIdx, int tid) {
    const uint4* s4 = reinterpret_cast<const uint4*>(g_img + (size_t)imgIdx * 16384);
    uint4* d4 = reinterpret_cast<uint4*>(dst);
#pragma unroll
    for (int i = 0; i < 8; i++) d4[tid + i * 256] = s4[tid + i * 256];
}

// load + split one window of x into XH/XL (256 threads)
__device__ __forceinline__ void load_x(const float* __restrict__ xw, char* smem, int tid) {
#pragma unroll
    for (int i = 0; i < 16; i++) {
        int idx4 = i * 256 + tid;
        int row = idx4 >> 5, col4 = idx4 & 31;
        float4 v = reinterpret_cast<const float4*>(xw)[idx4];
        __half h0 = __float2half_rn(v.x), h1 = __float2half_rn(v.y);
        __half h2 = __float2half_rn(v.z), h3 = __float2half_rn(v.w);
        uint32_t off = toff(row, col4 * 8);
        *reinterpret_cast<uint2*>(smem + XH + off) =
            make_uint2(pack2h(h0, h1), pack2h(h2, h3));
        *reinterpret_cast<uint2*>(smem + XL + off) = make_uint2(
            pack2h(__float2half_rn(v.x - __half2float(h0)),
                   __float2half_rn(v.y - __half2float(h1))),
            pack2h(__float2half_rn(v.z - __half2float(h2)),
                   __float2half_rn(v.w - __half2float(h3))));
    }
}

// ---- 3-term GEMM (32x64 tile): A hi/lo (2 mt), B hi/lo (4 ng @ bRow0) ----
__device__ __forceinline__ void gemm3_m2(float (&c)[2][8][4],
                                         uint32_t aBase, uint32_t bBase,
                                         int rowBase, int arl, int acb,
                                         int brl, int bcb, int bRow0) {
#pragma unroll
    for (int mt = 0; mt < 2; mt++)
#pragma unroll
        for (int nt = 0; nt < 8; nt++)
#pragma unroll
            for (int i = 0; i < 4; i++) c[mt][nt][i] = 0.0f;
#pragma unroll 1
    for (int kt = 0; kt < 8; kt++) {
        uint32_t ah[2][4], al[2][4];
#pragma unroll
        for (int mt = 0; mt < 2; mt++) {
            int arow = rowBase + mt * 16 + arl;
            uint32_t off = (uint32_t)(arow * 256 + (((kt * 2 + acb) ^ (arow & 7)) << 4));
            ldsm4(ah[mt], aBase + off);
            ldsm4(al[mt], aBase + 32768u + off);
        }
#pragma unroll
        for (int ng = 0; ng < 4; ng++) {
            int brow = bRow0 + ng * 16 + brl;
            uint32_t boff = (uint32_t)(brow * 256 + (((kt * 2 + bcb) ^ (brow & 7)) << 4));
            uint32_t bh[4], bl[4];
            ldsm4(bh, bBase + boff);
            ldsm4(bl, bBase + 32768u + boff);
#pragma unroll
            for (int mt = 0; mt < 2; mt++)
#pragma unroll
                for (int s = 0; s < 2; s++) {
                    float* cc = c[mt][ng * 2 + s];
                    mma16816(cc, ah[mt], bh[2 * s], bh[2 * s + 1]);
                    mma16816(cc, ah[mt], bl[2 * s], bl[2 * s + 1]);
                    mma16816(cc, al[mt], bh[2 * s], bh[2 * s + 1]);
                }
        }
    }
}

// ---- 1-term GEMM (32x64 tile): A single image (2 mt), B single (4 ng) ----
__device__ __forceinline__ void gemm1_m2(float (&c)[2][8][4],
                                         uint32_t aBase, uint32_t bBase,
                                         int rowBase, int arl, int acb,
                                         int brl, int bcb, int bRow0) {
#pragma unroll
    for (int mt = 0; mt < 2; mt++)
#pragma unroll
        for (int nt = 0; nt < 8; nt++)
#pragma unroll
            for (int i = 0; i < 4; i++) c[mt][nt][i] = 0.0f;
#pragma unroll 1
    for (int kt = 0; kt < 8; kt++) {
        uint32_t ah[2][4];
#pragma unroll
        for (int mt = 0; mt < 2; mt++) {
            int arow = rowBase + mt * 16 + arl;
            uint32_t off = (uint32_t)(arow * 256 + (((kt * 2 + acb) ^ (arow & 7)) << 4));
            ldsm4(ah[mt], aBase + off);
        }
#pragma unroll
        for (int ng = 0; ng < 4; ng++) {
            int brow = bRow0 + ng * 16 + brl;
            uint32_t boff = (uint32_t)(brow * 256 + (((kt * 2 + bcb) ^ (brow & 7)) << 4));
            uint32_t bh[4];
            ldsm4(bh, bBase + boff);
#pragma unroll
            for (int mt = 0; mt < 2; mt++)
#pragma unroll
                for (int s = 0; s < 2; s++)
                    mma16816(c[mt][ng * 2 + s], ah[mt], bh[2 * s], bh[2 * s + 1]);
        }
    }
}

__global__ void __launch_bounds__(256, 1)
win_attn(const float* __restrict__ x, const float* __restrict__ bv,
         float* __restrict__ out, int nwin) {
    extern __shared__ char smem_raw[];
    uint32_t sraw = smem_u32(smem_raw);
    uint32_t sb = (sraw + 1023u) & ~1023u;
    char* smem = smem_raw + (sb - sraw);

    const int tid = threadIdx.x, wid = tid >> 5, lane = tid & 31;
    const int mq = wid & 3, nh = wid >> 2;

    float* sred = reinterpret_cast<float*>(smem + OFF_SRED);

    copy_img32(smem + MH, 0, tid);
    copy_img32(smem + MH + 32768, 1, tid);
    copy_img32(smem + WVH, 2, tid);

    // ldmatrix lane mappings
    const int arl = (lane & 7) + ((lane >> 3) & 1) * 8, acb = (lane >> 4) & 1;
    const int brl = (lane & 7) + ((lane >> 4) & 1) * 8, bcb = (lane >> 3) & 1;
    const int rq = lane >> 2, cq = 2 * (lane & 3);
    const int rowBase = mq * 32;
    const int colBase = nh * 64;

    // per-thread bias registers
    float rr[8][2], bvr[2][2];
#pragma unroll
    for (int nt = 0; nt < 8; nt++) {
        rr[nt][0] = g_r[colBase + nt * 8 + cq];
        rr[nt][1] = g_r[colBase + nt * 8 + cq + 1];
    }
#pragma unroll
    for (int mt = 0; mt < 2; mt++)
#pragma unroll
        for (int h = 0; h < 2; h++)
            bvr[mt][h] = bv[rowBase + mt * 16 + h * 8 + rq];

    float c[2][8][4], cv[2][8][4];

    int w = blockIdx.x;
    if (w < nwin) load_x(x + (size_t)w * (WIN * 128), smem, tid);
    __syncthreads();                     // x(w0) + images ready

    while (w < nwin) {
        // ---- G1 (3-term): t = x M^T (+r) -> T_HI/T_LO ----
        gemm3_m2(c, sb + XH, sb + MH, rowBase, arl, acb, brl, bcb, colBase);
#pragma unroll
        for (int mt = 0; mt < 2; mt++)
#pragma unroll
            for (int h = 0; h < 2; h++) {
                int row = rowBase + mt * 16 + h * 8 + rq;
#pragma unroll
                for (int nt = 0; nt < 8; nt++) {
                    int col = colBase + nt * 8 + cq;
                    float v0 = c[mt][nt][2 * h] + rr[nt][0];
                    float v1 = c[mt][nt][2 * h + 1] + rr[nt][1];
                    __half h0 = __float2half_rn(v0), h1 = __float2half_rn(v1);
                    uint32_t o = toff(row, col * 2);
                    *reinterpret_cast<uint32_t*>(smem + T_HI + o) = pack2h(h0, h1);
                    *reinterpret_cast<uint32_t*>(smem + T_LO + o) =
                        pack2h(__float2half_rn(v0 - __half2float(h0)),
                               __float2half_rn(v1 - __half2float(h1)));
                }
            }
        __syncthreads();                 // (1) full-k T images ready (cross-warp!)

        // ---- G2 (3-term): S = t x^T (A = T images, full k) ----
        gemm3_m2(c, sb + T_HI, sb + XH, rowBase, arl, acb, brl, bcb, colBase);

        // ---- softmax partials (this half's 64 cols) ----
        float msav[2][2];
#pragma unroll
        for (int mt = 0; mt < 2; mt++)
#pragma unroll
            for (int h = 0; h < 2; h++) {
                float m = -1e30f;
#pragma unroll
                for (int nt = 0; nt < 8; nt++)
                    m = fmaxf(m, fmaxf(c[mt][nt][2 * h], c[mt][nt][2 * h + 1]));
                m = fmaxf(m, __shfl_xor_sync(0xffffffffu, m, 1));
                m = fmaxf(m, __shfl_xor_sync(0xffffffffu, m, 2));
                float s = 0.0f;
#pragma unroll
                for (int nt = 0; nt < 8; nt++) {
                    float e0 = __expf(c[mt][nt][2 * h] - m);
                    float e1 = __expf(c[mt][nt][2 * h + 1] - m);
                    c[mt][nt][2 * h] = e0;
                    c[mt][nt][2 * h + 1] = e1;
                    s += e0 + e1;
                }
                s += __shfl_xor_sync(0xffffffffu, s, 1);
                s += __shfl_xor_sync(0xffffffffu, s, 2);
                msav[mt][h] = m;
                if ((lane & 3) == 0) {
                    int row = rowBase + mt * 16 + h * 8 + rq;
                    *reinterpret_cast<float2*>(sred + row * 4 + nh * 2) =
                        make_float2(m, s);
                }
            }

        // ---- G3 (1-term): vT = Wvh xh^T (+bv) -> T_LO (tl dead after G2) ----
        gemm1_m2(cv, sb + WVH, sb + XH, rowBase, arl, acb, brl, bcb, colBase);
#pragma unroll
        for (int mt = 0; mt < 2; mt++)
#pragma unroll
            for (int h = 0; h < 2; h++) {
                int row = rowBase + mt * 16 + h * 8 + rq;
                float br = bvr[mt][h];
#pragma unroll
                for (int nt = 0; nt < 8; nt++) {
                    int col = colBase + nt * 8 + cq;
                    *reinterpret_cast<uint32_t*>(smem + T_LO + toff(row, col * 2)) =
                        pack2h(__float2half_rn(cv[mt][nt][2 * h] + br),
                               __float2half_rn(cv[mt][nt][2 * h + 1] + br));
                }
            }
        __syncthreads();                 // (2) vT + sred visible; all X reads done

        // ---- finish softmax; P -> T_HI ----
#pragma unroll
        for (int mt = 0; mt < 2; mt++)
#pragma unroll
            for (int h = 0; h < 2; h++) {
                int row = rowBase + mt * 16 + h * 8 + rq;
                float2 p0 = *reinterpret_cast<float2*>(sred + row * 4);
                float2 p1 = *reinterpret_cast<float2*>(sred + row * 4 + 2);
                float M = fmaxf(p0.x, p1.x);
                float S = p0.y * __expf(p0.x - M) + p1.y * __expf(p1.x - M);
                float scale = __expf(msav[mt][h] - M) / S;
#pragma unroll
                for (int nt = 0; nt < 8; nt++) {
                    int col = colBase + nt * 8 + cq;
                    *reinterpret_cast<uint32_t*>(smem + T_HI + toff(row, col * 2)) =
                        pack2h(__float2half_rn(c[mt][nt][2 * h] * scale),
                               __float2half_rn(c[mt][nt][2 * h + 1] * scale));
                }
            }
        __syncthreads();                 // (3) full-k P image ready (cross-warp!)

        // ---- overlap: load x for next window while G4 runs ----
        int wn = w + gridDim.x;
        if (wn < nwin) load_x(x + (size_t)wn * (WIN * 128), smem, tid);

        // ---- G4 (1-term): O = Ph vT^T -> out ----
        gemm1_m2(c, sb + T_HI, sb + T_LO, rowBase, arl, acb, brl, bcb, colBase);
        {
            float* outw = out + (size_t)w * (WIN * 128);
#pragma unroll
            for (int mt = 0; mt < 2; mt++)
#pragma unroll
                for (int h = 0; h < 2; h++) {
                    int row = rowBase + mt * 16 + h * 8 + rq;
#pragma unroll
                    for (int nt = 0; nt < 8; nt++) {
                        int col = colBase + nt * 8 + cq;
                        *reinterpret_cast<float2*>(outw + row * 128 + col) =
                            make_float2(c[mt][nt][2 * h], c[mt][nt][2 * h + 1]);
                    }
                }
        }
        __syncthreads();                 // (4) new x ready; T/vT dead

        w = wn;
    }
}

extern "C" void kernel_launch(void* const* d_in, const int* in_sizes, int n_in,
                              void* d_out, int out_size) {
    const float* x  = (const float*)d_in[0];
    const float* Wq = (const float*)d_in[1];
    const float* bq = (const float*)d_in[2];
    const float* Wk = (const float*)d_in[3];
    const float* Wv = (const float*)d_in[5];
    const float* bv = (const float*)d_in[6];
    float* out = (float*)d_out;

    int nwin = in_sizes[0] / (WIN * 128);

    prep_all<<<128, 128>>>(Wq, bq, Wk, Wv);

    cudaFuncSetAttribute(win_attn, cudaFuncAttributeMaxDynamicSharedMemorySize, SMEM_BYTES);
    int grid = nwin < 148 ? nwin : 148;
    win_attn<<<grid, 256, SMEM_BYTES>>>(x, bv, out, nwin);
}

// round 16
// speedup vs baseline: 1.3226x; 1.1448x over previous
#include <cuda_runtime.h>
#include <cuda_fp16.h>
#include <cstdint>
#include <cstddef>

// ============================================================================
// Windowed self-attention via mma.sync.m16n8k16 fp16 (split-fp32, fp32 acc).
// S-equiv = (x M^T + r) x^T  (M = Wq^T Wk, r = bq Wk; row-consts cancel in
// softmax). 4 GEMMs/window:
//   G3: vT = Wvh xh^T + bv (1-term)
//   G1: t  = x M^T + r     (3-term)  -> t-hi register fragments only
//   G2: S  = th x^T        (2-term: th*xh + th*xl)
//   G4: O  = Ph vT^T       (1-term, overlapped with next window's x load)
// 8 warps x 16 rows, 256 thr, persistent CTAs, 2 barriers/window.
// ============================================================================

#define WIN 128
// smem layout (bytes from 1KB-aligned base)
#define XH   0
#define XL   32768
#define MH   65536
#define WVH  131072
#define VTB  163840
#define OFF_BV 196608
#define OFF_R  197120
#define SMEM_PAYLOAD 197632
#define SMEM_BYTES (SMEM_PAYLOAD + 1024)

__device__ __forceinline__ uint32_t smem_u32(const void* p) {
    uint32_t a;
    asm("{ .reg .u64 t; cvta.to.shared.u64 t, %1; cvt.u32.u64 %0, t; }" : "=r"(a) : "l"(p));
    return a;
}

// Tile: 128 rows x 128 fp16 (256B/row, 16 chunks of 16B), XOR-swizzled.
__device__ __forceinline__ uint32_t toff(int row, int byteCol) {
    int chunk = byteCol >> 4;
    return (uint32_t)(row * 256 + (((chunk ^ (row & 7)) << 4) | (byteCol & 15)));
}

__device__ __forceinline__ uint32_t pack2h(__half a, __half b) {
    return (uint32_t)__half_as_ushort(a) | ((uint32_t)__half_as_ushort(b) << 16);
}

__device__ __forceinline__ void ldsm4(uint32_t r[4], uint32_t addr) {
    asm volatile("ldmatrix.sync.aligned.m8n8.x4.shared.b16 {%0,%1,%2,%3}, [%4];"
                 : "=r"(r[0]), "=r"(r[1]), "=r"(r[2]), "=r"(r[3]) : "r"(addr));
}

__device__ __forceinline__ void mma16816(float* c, const uint32_t a[4],
                                         uint32_t b0, uint32_t b1) {
    asm volatile(
        "mma.sync.aligned.m16n8k16.row.col.f32.f16.f16.f32 "
        "{%0,%1,%2,%3}, {%4,%5,%6,%7}, {%8,%9}, {%0,%1,%2,%3};"
        : "+f"(c[0]), "+f"(c[1]), "+f"(c[2]), "+f"(c[3])
        : "r"(a[0]), "r"(a[1]), "r"(a[2]), "r"(a[3]), "r"(b0), "r"(b1));
}

// Pre-split + pre-swizzled images: [M^T hi, M^T lo, Wv hi]
__device__ __align__(16) __half g_img[3 * 16384];
__device__ float g_r[128];

// ---- prep kernel: M image, Wv image, r vector ----
__global__ void prep_all(const float* __restrict__ Wq, const float* __restrict__ bq,
                         const float* __restrict__ Wk, const float* __restrict__ Wv) {
    __shared__ float wkcol[128];
    __shared__ float red[4];
    int f = blockIdx.x, e = threadIdx.x;
    wkcol[e] = Wk[e * 128 + f];
    __syncthreads();
    float acc = 0.0f;
#pragma unroll 8
    for (int d = 0; d < 128; d++)
        acc += Wq[d * 128 + e] * wkcol[d];
    uint32_t o = toff(f, e * 2) >> 1;
    {
        __half h = __float2half_rn(acc);
        g_img[o] = h;
        g_img[16384 + o] = __float2half_rn(acc - __half2float(h));
    }
    g_img[2 * 16384 + o] = __float2half_rn(Wv[f * 128 + e]);
    float p = bq[e] * wkcol[e];
#pragma unroll
    for (int m = 16; m >= 1; m >>= 1) p += __shfl_xor_sync(0xffffffffu, p, m);
    if ((e & 31) == 0) red[e >> 5] = p;
    __syncthreads();
    if (e == 0) g_r[f] = red[0] + red[1] + red[2] + red[3];
}

// copy pre-swizzled 32KB image into smem (256 threads)
__device__ __forceinline__ void copy_img32(char* dst, int imgIdx, int tid) {
    const uint4* s4 = reinterpret_cast<const uint4*>(g_img + (size_t)imgIdx * 16384);
    uint4* d4 = reinterpret_cast<uint4*>(dst);
#pragma unroll
    for (int i = 0; i < 8; i++) d4[tid + i * 256] = s4[tid + i * 256];
}

// load + split one window of x into XH/XL (256 threads)
__device__ __forceinline__ void load_x(const float* __restrict__ xw, char* smem, int tid) {
#pragma unroll
    for (int i = 0; i < 16; i++) {
        int idx4 = i * 256 + tid;
        int row = idx4 >> 5, col4 = idx4 & 31;
        float4 v = reinterpret_cast<const float4*>(xw)[idx4];
        __half h0 = __float2half_rn(v.x), h1 = __float2half_rn(v.y);
        __half h2 = __float2half_rn(v.z), h3 = __float2half_rn(v.w);
        uint32_t off = toff(row, col4 * 8);
        *reinterpret_cast<uint2*>(smem + XH + off) =
            make_uint2(pack2h(h0, h1), pack2h(h2, h3));
        *reinterpret_cast<uint2*>(smem + XL + off) = make_uint2(
            pack2h(__float2half_rn(v.x - __half2float(h0)),
                   __float2half_rn(v.y - __half2float(h1))),
            pack2h(__float2half_rn(v.z - __half2float(h2)),
                   __float2half_rn(v.w - __half2float(h3))));
    }
}

// ---- 3-term GEMM: A smem hi/lo (aBase, aBase+32KB), B smem hi/lo ----
__device__ __forceinline__ void gemm3_sa(float (&c)[16][4],
                                         uint32_t aBase, uint32_t bBase,
                                         int arow, int acb, int brl, int bcb) {
#pragma unroll
    for (int nt = 0; nt < 16; nt++)
#pragma unroll
        for (int i = 0; i < 4; i++) c[nt][i] = 0.0f;
#pragma unroll 1
    for (int kt = 0; kt < 8; kt++) {
        uint32_t ah[4], al[4];
        {
            uint32_t off = (uint32_t)(arow * 256 + (((kt * 2 + acb) ^ (arow & 7)) << 4));
            ldsm4(ah, aBase + off);
            ldsm4(al, aBase + 32768u + off);
        }
#pragma unroll
        for (int ng = 0; ng < 8; ng++) {
            int brow = ng * 16 + brl;
            uint32_t boff = (uint32_t)(brow * 256 + (((kt * 2 + bcb) ^ (brow & 7)) << 4));
            uint32_t bh[4], bl[4];
            ldsm4(bh, bBase + boff);
            ldsm4(bl, bBase + 32768u + boff);
#pragma unroll
            for (int s = 0; s < 2; s++) {
                float* cc = c[ng * 2 + s];
                mma16816(cc, ah, bh[2 * s], bh[2 * s + 1]);
                mma16816(cc, ah, bl[2 * s], bl[2 * s + 1]);
                mma16816(cc, al, bh[2 * s], bh[2 * s + 1]);
            }
        }
    }
}

// ---- 2-term GEMM: A register fragments (hi only), B smem hi/lo ----
// C = th*Bh^T + th*Bl^T   (used for G2: S = th (xh+xl)^T)
__device__ __forceinline__ void gemm2_ra(float (&c)[16][4],
                                         const uint32_t (&th)[16][2],
                                         uint32_t bBase, int brl, int bcb) {
#pragma unroll
    for (int nt = 0; nt < 16; nt++)
#pragma unroll
        for (int i = 0; i < 4; i++) c[nt][i] = 0.0f;
#pragma unroll
    for (int kt = 0; kt < 8; kt++) {
        uint32_t ah[4] = {th[2 * kt][0], th[2 * kt][1], th[2 * kt + 1][0], th[2 * kt + 1][1]};
#pragma unroll
        for (int ng = 0; ng < 8; ng++) {
            int brow = ng * 16 + brl;
            uint32_t boff = (uint32_t)(brow * 256 + (((kt * 2 + bcb) ^ (brow & 7)) << 4));
            uint32_t bh[4], bl[4];
            ldsm4(bh, bBase + boff);
            ldsm4(bl, bBase + 32768u + boff);
#pragma unroll
            for (int s = 0; s < 2; s++) {
                float* cc = c[ng * 2 + s];
                mma16816(cc, ah, bh[2 * s], bh[2 * s + 1]);
                mma16816(cc, ah, bl[2 * s], bl[2 * s + 1]);
            }
        }
    }
}

// ---- 1-term GEMM: A smem single image, B smem single image ----
__device__ __forceinline__ void gemm1_sa(float (&c)[16][4],
                                         uint32_t aBase, uint32_t bBase,
                                         int arow, int acb, int brl, int bcb) {
#pragma unroll
    for (int nt = 0; nt < 16; nt++)
#pragma unroll
        for (int i = 0; i < 4; i++) c[nt][i] = 0.0f;
#pragma unroll 1
    for (int kt = 0; kt < 8; kt++) {
        uint32_t ah[4];
        {
            uint32_t off = (uint32_t)(arow * 256 + (((kt * 2 + acb) ^ (arow & 7)) << 4));
            ldsm4(ah, aBase + off);
        }
#pragma unroll
        for (int ng = 0; ng < 8; ng++) {
            int brow = ng * 16 + brl;
            uint32_t boff = (uint32_t)(brow * 256 + (((kt * 2 + bcb) ^ (brow & 7)) << 4));
            uint32_t bh[4];
            ldsm4(bh, bBase + boff);
#pragma unroll
            for (int s = 0; s < 2; s++)
                mma16816(c[ng * 2 + s], ah, bh[2 * s], bh[2 * s + 1]);
        }
    }
}

// ---- 1-term GEMM: A register fragments (hi only), B smem single image ----
__device__ __forceinline__ void gemm1_ra(float (&c)[16][4],
                                         const uint32_t (&th)[16][2],
                                         uint32_t bBase, int brl, int bcb) {
#pragma unroll
    for (int nt = 0; nt < 16; nt++)
#pragma unroll
        for (int i = 0; i < 4; i++) c[nt][i] = 0.0f;
#pragma unroll
    for (int kt = 0; kt < 8; kt++) {
        uint32_t ah[4] = {th[2 * kt][0], th[2 * kt][1], th[2 * kt + 1][0], th[2 * kt + 1][1]};
#pragma unroll
        for (int ng = 0; ng < 8; ng++) {
            int brow = ng * 16 + brl;
            uint32_t boff = (uint32_t)(brow * 256 + (((kt * 2 + bcb) ^ (brow & 7)) << 4));
            uint32_t bh[4];
            ldsm4(bh, bBase + boff);
#pragma unroll
            for (int s = 0; s < 2; s++)
                mma16816(c[ng * 2 + s], ah, bh[2 * s], bh[2 * s + 1]);
        }
    }
}

// pack C fragments into hi-only fp16 A-fragments (for P)
__device__ __forceinline__ void pack_hi(const float (&c)[16][4], uint32_t (&h)[16][2]) {
#pragma unroll
    for (int nt = 0; nt < 16; nt++)
#pragma unroll
        for (int j = 0; j < 2; j++)
            h[nt][j] = pack2h(__float2half_rn(c[nt][2 * j]),
                              __float2half_rn(c[nt][2 * j + 1]));
}

// pack C fragments into hi-only fp16 A-fragments, adding per-col bias r (t)
__device__ __forceinline__ void pack_hi_bias(const float (&c)[16][4],
                                             uint32_t (&h)[16][2],
                                             const float* sr, int cq) {
#pragma unroll
    for (int nt = 0; nt < 16; nt++) {
        float rA = sr[nt * 8 + cq], rB = sr[nt * 8 + cq + 1];
#pragma unroll
        for (int j = 0; j < 2; j++)
            h[nt][j] = pack2h(__float2half_rn(c[nt][2 * j] + rA),
                              __float2half_rn(c[nt][2 * j + 1] + rB));
    }
}

__global__ void __launch_bounds__(256, 1)
win_attn(const float* __restrict__ x, const float* __restrict__ bv,
         float* __restrict__ out, int nwin) {
    extern __shared__ char smem_raw[];
    uint32_t sraw = smem_u32(smem_raw);
    uint32_t sb = (sraw + 1023u) & ~1023u;
    char* smem = smem_raw + (sb - sraw);

    const int tid = threadIdx.x, wid = tid >> 5, lane = tid & 31;

    float* sbv = reinterpret_cast<float*>(smem + OFF_BV);
    float* sr  = reinterpret_cast<float*>(smem + OFF_R);
    if (tid < 128) {
        sbv[tid] = bv[tid];
        sr[tid] = g_r[tid];
    }
    // resident weight images: M hi, M lo, Wv hi
    copy_img32(smem + MH, 0, tid);
    copy_img32(smem + MH + 32768, 1, tid);
    copy_img32(smem + WVH, 2, tid);

    // ldmatrix lane mappings
    const int arl = (lane & 7) + ((lane >> 3) & 1) * 8, acb = (lane >> 4) & 1;
    const int brl = (lane & 7) + ((lane >> 4) & 1) * 8, bcb = (lane >> 3) & 1;
    const int rq = lane >> 2, cq = 2 * (lane & 3);
    const int rowBase = wid * 16;
    const int arow = rowBase + arl;

    float c[16][4];
    uint32_t fh[16][2];              // A-fragments: t (hi), then P (hi)

    int w = blockIdx.x;
    if (w < nwin) load_x(x + (size_t)w * (WIN * 128), smem, tid);
    __syncthreads();                     // x(w0), images, biases ready

    while (w < nwin) {
        // ---- G3 (1-term): vT = Wvh xh^T ; +bv row ; -> VTB ----
        gemm1_sa(c, sb + WVH, sb + XH, arow, acb, brl, bcb);
#pragma unroll
        for (int h = 0; h < 2; h++) {
            int row = rowBase + h * 8 + rq;
            float br = sbv[row];
#pragma unroll
            for (int nt = 0; nt < 16; nt++) {
                int col = nt * 8 + cq;
                *reinterpret_cast<uint32_t*>(smem + VTB + toff(row, col * 2)) =
                    pack2h(__float2half_rn(c[nt][2 * h] + br),
                           __float2half_rn(c[nt][2 * h + 1] + br));
            }
        }

        // ---- G1 (3-term): t = x M^T ; t += r ; -> hi register fragments ----
        gemm3_sa(c, sb + XH, sb + MH, arow, acb, brl, bcb);
        pack_hi_bias(c, fh, sr, cq);

        // ---- G2 (2-term): S = th (xh + xl)^T ----
        gemm2_ra(c, fh, sb + XH, brl, bcb);

        // softmax on c -> P fragments (hi only)
#pragma unroll
        for (int h = 0; h < 2; h++) {
            float m = -1e30f;
#pragma unroll
            for (int nt = 0; nt < 16; nt++)
                m = fmaxf(m, fmaxf(c[nt][2 * h], c[nt][2 * h + 1]));
            m = fmaxf(m, __shfl_xor_sync(0xffffffffu, m, 1));
            m = fmaxf(m, __shfl_xor_sync(0xffffffffu, m, 2));
            float s = 0.0f;
#pragma unroll
            for (int nt = 0; nt < 16; nt++) {
                float e0 = __expf(c[nt][2 * h] - m);
                float e1 = __expf(c[nt][2 * h + 1] - m);
                c[nt][2 * h] = e0;
                c[nt][2 * h + 1] = e1;
                s += e0 + e1;
            }
            s += __shfl_xor_sync(0xffffffffu, s, 1);
            s += __shfl_xor_sync(0xffffffffu, s, 2);
            float inv = 1.0f / s;
#pragma unroll
            for (int nt = 0; nt < 16; nt++) {
                c[nt][2 * h] *= inv;
                c[nt][2 * h + 1] *= inv;
            }
        }
        pack_hi(c, fh);                  // P fragments (hi only)
        __syncthreads();                 // (2) vT visible; XH/XL dead everywhere

        // ---- overlap: load x for next window while G4 runs ----
        int wn = w + gridDim.x;
        if (wn < nwin) load_x(x + (size_t)wn * (WIN * 128), smem, tid);

        // ---- G4 (1-term): O = Ph vT^T -> out ----
        gemm1_ra(c, fh, sb + VTB, brl, bcb);
        {
            float* outw = out + (size_t)w * (WIN * 128);
#pragma unroll
            for (int h = 0; h < 2; h++) {
                int row = rowBase + h * 8 + rq;
#pragma unroll
                for (int nt = 0; nt < 16; nt++) {
                    int col = nt * 8 + cq;
                    *reinterpret_cast<float2*>(outw + row * 128 + col) =
                        make_float2(c[nt][2 * h], c[nt][2 * h + 1]);
                }
            }
        }
        __syncthreads();                 // (1) new x ready; VTB dead

        w = wn;
    }
}

extern "C" void kernel_launch(void* const* d_in, const int* in_sizes, int n_in,
                              void* d_out, int out_size) {
    const float* x  = (const float*)d_in[0];
    const float* Wq = (const float*)d_in[1];
    const float* bq = (const float*)d_in[2];
    const float* Wk = (const float*)d_in[3];
    const float* Wv = (const float*)d_in[5];
    const float* bv = (const float*)d_in[6];
    float* out = (float*)d_out;

    int nwin = in_sizes[0] / (WIN * 128);

    prep_all<<<128, 128>>>(Wq, bq, Wk, Wv);

    cudaFuncSetAttribute(win_attn, cudaFuncAttributeMaxDynamicSharedMemorySize, SMEM_BYTES);
    int grid = nwin < 148 ? nwin : 148;
    win_attn<<<grid, 256, SMEM_BYTES>>>(x, bv, out, nwin);
}

// round 17
// speedup vs baseline: 1.3519x; 1.0222x over previous
#include <cuda_runtime.h>
#include <cuda_fp16.h>
#include <cstdint>
#include <cstddef>

// ============================================================================
// Windowed self-attention via mma.sync.m16n8k16 fp16 (split-fp32, fp32 acc).
// S-equiv = (x M^T + r) x^T  (M = Wq^T Wk, r = bq Wk; row-consts cancel in
// softmax). 4 GEMMs/window:
//   G1: t  = x M^T + r     (3-term)  -> t-hi register fragments
//   G2: S  = th (xh+xl)^T  (2-term)  \ fused loop sharing xh B-tiles,
//   G3: vT = Wvh xh^T + bv (1-term)  / dual accumulator streams
//   G4: O  = Ph vT^T       (1-term, overlapped with next window's x load)
// 8 warps x 16 rows, 256 thr, persistent CTAs, 2 barriers/window.
// ============================================================================

#define WIN 128
// smem layout (bytes from 1KB-aligned base)
#define XH   0
#define XL   32768
#define MH   65536
#define WVH  131072
#define VTB  163840
#define OFF_BV 196608
#define OFF_R  197120
#define SMEM_PAYLOAD 197632
#define SMEM_BYTES (SMEM_PAYLOAD + 1024)

__device__ __forceinline__ uint32_t smem_u32(const void* p) {
    uint32_t a;
    asm("{ .reg .u64 t; cvta.to.shared.u64 t, %1; cvt.u32.u64 %0, t; }" : "=r"(a) : "l"(p));
    return a;
}

// Tile: 128 rows x 128 fp16 (256B/row, 16 chunks of 16B), XOR-swizzled.
__device__ __forceinline__ uint32_t toff(int row, int byteCol) {
    int chunk = byteCol >> 4;
    return (uint32_t)(row * 256 + (((chunk ^ (row & 7)) << 4) | (byteCol & 15)));
}

__device__ __forceinline__ uint32_t pack2h(__half a, __half b) {
    return (uint32_t)__half_as_ushort(a) | ((uint32_t)__half_as_ushort(b) << 16);
}

__device__ __forceinline__ void ldsm4(uint32_t r[4], uint32_t addr) {
    asm volatile("ldmatrix.sync.aligned.m8n8.x4.shared.b16 {%0,%1,%2,%3}, [%4];"
                 : "=r"(r[0]), "=r"(r[1]), "=r"(r[2]), "=r"(r[3]) : "r"(addr));
}

__device__ __forceinline__ void mma16816(float* c, const uint32_t a[4],
                                         uint32_t b0, uint32_t b1) {
    asm volatile(
        "mma.sync.aligned.m16n8k16.row.col.f32.f16.f16.f32 "
        "{%0,%1,%2,%3}, {%4,%5,%6,%7}, {%8,%9}, {%0,%1,%2,%3};"
        : "+f"(c[0]), "+f"(c[1]), "+f"(c[2]), "+f"(c[3])
        : "r"(a[0]), "r"(a[1]), "r"(a[2]), "r"(a[3]), "r"(b0), "r"(b1));
}

// Pre-split + pre-swizzled images: [M^T hi, M^T lo, Wv hi]
__device__ __align__(16) __half g_img[3 * 16384];
__device__ float g_r[128];

// ---- prep kernel: M image, Wv image, r vector ----
__global__ void prep_all(const float* __restrict__ Wq, const float* __restrict__ bq,
                         const float* __restrict__ Wk, const float* __restrict__ Wv) {
    __shared__ float wkcol[128];
    __shared__ float red[4];
    int f = blockIdx.x, e = threadIdx.x;
    wkcol[e] = Wk[e * 128 + f];
    __syncthreads();
    float acc = 0.0f;
#pragma unroll 8
    for (int d = 0; d < 128; d++)
        acc += Wq[d * 128 + e] * wkcol[d];
    uint32_t o = toff(f, e * 2) >> 1;
    {
        __half h = __float2half_rn(acc);
        g_img[o] = h;
        g_img[16384 + o] = __float2half_rn(acc - __half2float(h));
    }
    g_img[2 * 16384 + o] = __float2half_rn(Wv[f * 128 + e]);
    float p = bq[e] * wkcol[e];
#pragma unroll
    for (int m = 16; m >= 1; m >>= 1) p += __shfl_xor_sync(0xffffffffu, p, m);
    if ((e & 31) == 0) red[e >> 5] = p;
    __syncthreads();
    if (e == 0) g_r[f] = red[0] + red[1] + red[2] + red[3];
}

// copy pre-swizzled 32KB image into smem (256 threads)
__device__ __forceinline__ void copy_img32(char* dst, int imgIdx, int tid) {
    const uint4* s4 = reinterpret_cast<const uint4*>(g_img + (size_t)imgIdx * 16384);
    uint4* d4 = reinterpret_cast<uint4*>(dst);
#pragma unroll
    for (int i = 0; i < 8; i++) d4[tid + i * 256] = s4[tid + i * 256];
}

// load + split one window of x into XH/XL (256 threads)
__device__ __forceinline__ void load_x(const float* __restrict__ xw, char* smem, int tid) {
#pragma unroll
    for (int i = 0; i < 16; i++) {
        int idx4 = i * 256 + tid;
        int row = idx4 >> 5, col4 = idx4 & 31;
        float4 v = reinterpret_cast<const float4*>(xw)[idx4];
        __half h0 = __float2half_rn(v.x), h1 = __float2half_rn(v.y);
        __half h2 = __float2half_rn(v.z), h3 = __float2half_rn(v.w);
        uint32_t off = toff(row, col4 * 8);
        *reinterpret_cast<uint2*>(smem + XH + off) =
            make_uint2(pack2h(h0, h1), pack2h(h2, h3));
        *reinterpret_cast<uint2*>(smem + XL + off) = make_uint2(
            pack2h(__float2half_rn(v.x - __half2float(h0)),
                   __float2half_rn(v.y - __half2float(h1))),
            pack2h(__float2half_rn(v.z - __half2float(h2)),
                   __float2half_rn(v.w - __half2float(h3))));
    }
}

// ---- 3-term GEMM: A smem hi/lo (aBase, aBase+32KB), B smem hi/lo ----
__device__ __forceinline__ void gemm3_sa(float (&c)[16][4],
                                         uint32_t aBase, uint32_t bBase,
                                         int arow, int acb, int brl, int bcb) {
#pragma unroll
    for (int nt = 0; nt < 16; nt++)
#pragma unroll
        for (int i = 0; i < 4; i++) c[nt][i] = 0.0f;
#pragma unroll 1
    for (int kt = 0; kt < 8; kt++) {
        uint32_t ah[4], al[4];
        {
            uint32_t off = (uint32_t)(arow * 256 + (((kt * 2 + acb) ^ (arow & 7)) << 4));
            ldsm4(ah, aBase + off);
            ldsm4(al, aBase + 32768u + off);
        }
#pragma unroll
        for (int ng = 0; ng < 8; ng++) {
            int brow = ng * 16 + brl;
            uint32_t boff = (uint32_t)(brow * 256 + (((kt * 2 + bcb) ^ (brow & 7)) << 4));
            uint32_t bh[4], bl[4];
            ldsm4(bh, bBase + boff);
            ldsm4(bl, bBase + 32768u + boff);
#pragma unroll
            for (int s = 0; s < 2; s++) {
                float* cc = c[ng * 2 + s];
                mma16816(cc, ah, bh[2 * s], bh[2 * s + 1]);
                mma16816(cc, ah, bl[2 * s], bl[2 * s + 1]);
                mma16816(cc, al, bh[2 * s], bh[2 * s + 1]);
            }
        }
    }
}

// ---- fused G2+G3: shared xh B-tiles, dual accumulator streams ----
// c2: S  = th*xh^T + th*xl^T  (2-term, A = th register fragments)
// c3: vT = Wvh*xh^T           (1-term, A = Wv hi smem image)
__device__ __forceinline__ void gemm_g2g3(float (&c2)[16][4], float (&c3)[16][4],
                                          const uint32_t (&th)[16][2],
                                          uint32_t xh, uint32_t xl, uint32_t wv,
                                          int arow, int acb, int brl, int bcb) {
#pragma unroll
    for (int nt = 0; nt < 16; nt++)
#pragma unroll
        for (int i = 0; i < 4; i++) { c2[nt][i] = 0.0f; c3[nt][i] = 0.0f; }
#pragma unroll
    for (int kt = 0; kt < 8; kt++) {
        uint32_t ah3[4];
        {
            uint32_t aoff = (uint32_t)(arow * 256 + (((kt * 2 + acb) ^ (arow & 7)) << 4));
            ldsm4(ah3, wv + aoff);
        }
        uint32_t ah2[4] = {th[2 * kt][0], th[2 * kt][1], th[2 * kt + 1][0], th[2 * kt + 1][1]};
#pragma unroll
        for (int ng = 0; ng < 8; ng++) {
            int brow = ng * 16 + brl;
            uint32_t boff = (uint32_t)(brow * 256 + (((kt * 2 + bcb) ^ (brow & 7)) << 4));
            uint32_t bh[4], bl[4];
            ldsm4(bh, xh + boff);
            ldsm4(bl, xl + boff);
#pragma unroll
            for (int s = 0; s < 2; s++) {
                float* cS = c2[ng * 2 + s];
                float* cV = c3[ng * 2 + s];
                mma16816(cS, ah2, bh[2 * s], bh[2 * s + 1]);
                mma16816(cV, ah3, bh[2 * s], bh[2 * s + 1]);
                mma16816(cS, ah2, bl[2 * s], bl[2 * s + 1]);
            }
        }
    }
}

// ---- 1-term GEMM: A register fragments (hi only), B smem single image ----
__device__ __forceinline__ void gemm1_ra(float (&c)[16][4],
                                         const uint32_t (&th)[16][2],
                                         uint32_t bBase, int brl, int bcb) {
#pragma unroll
    for (int nt = 0; nt < 16; nt++)
#pragma unroll
        for (int i = 0; i < 4; i++) c[nt][i] = 0.0f;
#pragma unroll
    for (int kt = 0; kt < 8; kt++) {
        uint32_t ah[4] = {th[2 * kt][0], th[2 * kt][1], th[2 * kt + 1][0], th[2 * kt + 1][1]};
#pragma unroll
        for (int ng = 0; ng < 8; ng++) {
            int brow = ng * 16 + brl;
            uint32_t boff = (uint32_t)(brow * 256 + (((kt * 2 + bcb) ^ (brow & 7)) << 4));
            uint32_t bh[4];
            ldsm4(bh, bBase + boff);
#pragma unroll
            for (int s = 0; s < 2; s++)
                mma16816(c[ng * 2 + s], ah, bh[2 * s], bh[2 * s + 1]);
        }
    }
}

// pack C fragments into hi-only fp16 A-fragments (for P)
__device__ __forceinline__ void pack_hi(const float (&c)[16][4], uint32_t (&h)[16][2]) {
#pragma unroll
    for (int nt = 0; nt < 16; nt++)
#pragma unroll
        for (int j = 0; j < 2; j++)
            h[nt][j] = pack2h(__float2half_rn(c[nt][2 * j]),
                              __float2half_rn(c[nt][2 * j + 1]));
}

// pack C fragments into hi-only fp16 A-fragments, adding per-col bias r (t)
__device__ __forceinline__ void pack_hi_bias(const float (&c)[16][4],
                                             uint32_t (&h)[16][2],
                                             const float* sr, int cq) {
#pragma unroll
    for (int nt = 0; nt < 16; nt++) {
        float rA = sr[nt * 8 + cq], rB = sr[nt * 8 + cq + 1];
#pragma unroll
        for (int j = 0; j < 2; j++)
            h[nt][j] = pack2h(__float2half_rn(c[nt][2 * j] + rA),
                              __float2half_rn(c[nt][2 * j + 1] + rB));
    }
}

__global__ void __launch_bounds__(256, 1)
win_attn(const float* __restrict__ x, const float* __restrict__ bv,
         float* __restrict__ out, int nwin) {
    extern __shared__ char smem_raw[];
    uint32_t sraw = smem_u32(smem_raw);
    uint32_t sb = (sraw + 1023u) & ~1023u;
    char* smem = smem_raw + (sb - sraw);

    const int tid = threadIdx.x, wid = tid >> 5, lane = tid & 31;

    float* sbv = reinterpret_cast<float*>(smem + OFF_BV);
    float* sr  = reinterpret_cast<float*>(smem + OFF_R);
    if (tid < 128) {
        sbv[tid] = bv[tid];
        sr[tid] = g_r[tid];
    }
    // resident weight images: M hi, M lo, Wv hi
    copy_img32(smem + MH, 0, tid);
    copy_img32(smem + MH + 32768, 1, tid);
    copy_img32(smem + WVH, 2, tid);

    // ldmatrix lane mappings
    const int arl = (lane & 7) + ((lane >> 3) & 1) * 8, acb = (lane >> 4) & 1;
    const int brl = (lane & 7) + ((lane >> 4) & 1) * 8, bcb = (lane >> 3) & 1;
    const int rq = lane >> 2, cq = 2 * (lane & 3);
    const int rowBase = wid * 16;
    const int arow = rowBase + arl;

    float c2[16][4], c3[16][4];
    uint32_t fh[16][2];              // A-fragments: t (hi), then P (hi)

    int w = blockIdx.x;
    if (w < nwin) load_x(x + (size_t)w * (WIN * 128), smem, tid);
    __syncthreads();                     // x(w0), images, biases ready

    while (w < nwin) {
        // ---- G1 (3-term): t = x M^T ; t += r ; -> hi register fragments ----
        gemm3_sa(c2, sb + XH, sb + MH, arow, acb, brl, bcb);
        pack_hi_bias(c2, fh, sr, cq);

        // ---- fused G2+G3: S (2-term) and vT (1-term) sharing xh tiles ----
        gemm_g2g3(c2, c3, fh, sb + XH, sb + XL, sb + WVH, arow, acb, brl, bcb);

        // softmax on c2 -> P fragments (hi only)
#pragma unroll
        for (int h = 0; h < 2; h++) {
            float m = -1e30f;
#pragma unroll
            for (int nt = 0; nt < 16; nt++)
                m = fmaxf(m, fmaxf(c2[nt][2 * h], c2[nt][2 * h + 1]));
            m = fmaxf(m, __shfl_xor_sync(0xffffffffu, m, 1));
            m = fmaxf(m, __shfl_xor_sync(0xffffffffu, m, 2));
            float s = 0.0f;
#pragma unroll
            for (int nt = 0; nt < 16; nt++) {
                float e0 = __expf(c2[nt][2 * h] - m);
                float e1 = __expf(c2[nt][2 * h + 1] - m);
                c2[nt][2 * h] = e0;
                c2[nt][2 * h + 1] = e1;
                s += e0 + e1;
            }
            s += __shfl_xor_sync(0xffffffffu, s, 1);
            s += __shfl_xor_sync(0xffffffffu, s, 2);
            float inv = 1.0f / s;
#pragma unroll
            for (int nt = 0; nt < 16; nt++) {
                c2[nt][2 * h] *= inv;
                c2[nt][2 * h + 1] *= inv;
            }
        }
        pack_hi(c2, fh);                 // P fragments (hi only)

        // vT epilogue (c3 + bv row) -> VTB
#pragma unroll
        for (int h = 0; h < 2; h++) {
            int row = rowBase + h * 8 + rq;
            float br = sbv[row];
#pragma unroll
            for (int nt = 0; nt < 16; nt++) {
                int col = nt * 8 + cq;
                *reinterpret_cast<uint32_t*>(smem + VTB + toff(row, col * 2)) =
                    pack2h(__float2half_rn(c3[nt][2 * h] + br),
                           __float2half_rn(c3[nt][2 * h + 1] + br));
            }
        }
        __syncthreads();                 // (2) vT visible; XH/XL dead everywhere

        // ---- overlap: load x for next window while G4 runs ----
        int wn = w + gridDim.x;
        if (wn < nwin) load_x(x + (size_t)wn * (WIN * 128), smem, tid);

        // ---- G4 (1-term): O = Ph vT^T -> out ----
        gemm1_ra(c2, fh, sb + VTB, brl, bcb);
        {
            float* outw = out + (size_t)w * (WIN * 128);
#pragma unroll
            for (int h = 0; h < 2; h++) {
                int row = rowBase + h * 8 + rq;
#pragma unroll
                for (int nt = 0; nt < 16; nt++) {
                    int col = nt * 8 + cq;
                    *reinterpret_cast<float2*>(outw + row * 128 + col) =
                        make_float2(c2[nt][2 * h], c2[nt][2 * h + 1]);
                }
            }
        }
        __syncthreads();                 // (1) new x ready; VTB dead

        w = wn;
    }
}

extern "C" void kernel_launch(void* const* d_in, const int* in_sizes, int n_in,
                              void* d_out, int out_size) {
    const float* x  = (const float*)d_in[0];
    const float* Wq = (const float*)d_in[1];
    const float* bq = (const float*)d_in[2];
    const float* Wk = (const float*)d_in[3];
    const float* Wv = (const float*)d_in[5];
    const float* bv = (const float*)d_in[6];
    float* out = (float*)d_out;

    int nwin = in_sizes[0] / (WIN * 128);

    prep_all<<<128, 128>>>(Wq, bq, Wk, Wv);

    cudaFuncSetAttribute(win_attn, cudaFuncAttributeMaxDynamicSharedMemorySize, SMEM_BYTES);
    int grid = nwin < 148 ? nwin : 148;
    win_attn<<<grid, 256, SMEM_BYTES>>>(x, bv, out, nwin);
}